// round 4
// baseline (speedup 1.0000x reference)
#include <cuda_runtime.h>
#include <cstdint>

// Problem constants (fixed-shape problem)
#define B_SZ   4
#define T_SEQ  2048
#define E_DIM  1024
#define NH     16
#define HD     64
#define M_TOT  (B_SZ * T_SEQ)   // 8192

// ---------------------------------------------------------------------------
// Scratch (allocation-free rule: __device__ globals)
// ---------------------------------------------------------------------------
__device__ float g_q[(size_t)M_TOT * E_DIM];    // [B,H,T,D]
__device__ float g_k[(size_t)M_TOT * E_DIM];    // [B,H,T,D]
__device__ float g_v[(size_t)M_TOT * E_DIM];    // [B,H,T,D]
__device__ float g_ctx[(size_t)M_TOT * E_DIM];  // [B,T,E]

// ---------------------------------------------------------------------------
// tf32 helpers
// ---------------------------------------------------------------------------
__device__ __forceinline__ uint32_t f2tf(float x) {
    uint32_t r;
    asm("cvt.rna.tf32.f32 %0, %1;" : "=r"(r) : "f"(x));
    return r;
}

// D = A(16x8) * B(8x8) + D, tf32 inputs, fp32 accum
__device__ __forceinline__ void mma8(float* c, const uint32_t* a, const uint32_t* b) {
    asm volatile(
        "mma.sync.aligned.m16n8k8.row.col.f32.tf32.tf32.f32 "
        "{%0,%1,%2,%3}, {%4,%5,%6,%7}, {%8,%9}, {%0,%1,%2,%3};\n"
        : "+f"(c[0]), "+f"(c[1]), "+f"(c[2]), "+f"(c[3])
        : "r"(a[0]), "r"(a[1]), "r"(a[2]), "r"(a[3]), "r"(b[0]), "r"(b[1]));
}

// ---------------------------------------------------------------------------
// GEMM: Y = X @ W^T + bias.  X:[M,1024] W:[1024,1024] (row n holds W[n,:])
// Block tile 128x64, BK=32, 256 threads = 8 warps (4 M x 2 N), warp tile 32x32.
// split=1: write Y in [B,H,T,D] layout (head split); split=0: plain [M,E].
// ---------------------------------------------------------------------------
__global__ __launch_bounds__(256) void gemm_bias(
    const float* __restrict__ X, const float* __restrict__ W,
    const float* __restrict__ bias, float* __restrict__ Y, int split)
{
    __shared__ uint32_t As[128][36];  // rows m, cols k (tf32 bits), pad 4
    __shared__ uint32_t Bs[64][36];   // rows n, cols k

    const int tid  = threadIdx.x;
    const int warp = tid >> 5, lane = tid & 31;
    const int wm   = warp >> 1, wn = warp & 1;
    const int g    = lane >> 2, t = lane & 3;
    const int m0   = blockIdx.x * 128;
    const int n0   = blockIdx.y * 64;

    float acc[2][4][4];
#pragma unroll
    for (int i = 0; i < 2; i++)
#pragma unroll
        for (int j = 0; j < 4; j++)
#pragma unroll
            for (int r = 0; r < 4; r++) acc[i][j][r] = 0.f;

    for (int k0 = 0; k0 < E_DIM; k0 += 32) {
        // Load A tile 128x32 (4 float4 per thread)
#pragma unroll
        for (int i = 0; i < 4; i++) {
            int idx = tid + i * 256;
            int r = idx >> 3, c = (idx & 7) << 2;
            float4 v = *(const float4*)(X + (size_t)(m0 + r) * E_DIM + k0 + c);
            As[r][c + 0] = f2tf(v.x); As[r][c + 1] = f2tf(v.y);
            As[r][c + 2] = f2tf(v.z); As[r][c + 3] = f2tf(v.w);
        }
        // Load B tile 64x32 (2 float4 per thread)
#pragma unroll
        for (int i = 0; i < 2; i++) {
            int idx = tid + i * 256;
            int r = idx >> 3, c = (idx & 7) << 2;
            float4 v = *(const float4*)(W + (size_t)(n0 + r) * E_DIM + k0 + c);
            Bs[r][c + 0] = f2tf(v.x); Bs[r][c + 1] = f2tf(v.y);
            Bs[r][c + 2] = f2tf(v.z); Bs[r][c + 3] = f2tf(v.w);
        }
        __syncthreads();

#pragma unroll
        for (int kk = 0; kk < 32; kk += 8) {
            uint32_t a[2][4], b[4][2];
#pragma unroll
            for (int mt = 0; mt < 2; mt++) {
                int row = wm * 32 + mt * 16;
                a[mt][0] = As[row + g][kk + t];
                a[mt][1] = As[row + 8 + g][kk + t];
                a[mt][2] = As[row + g][kk + t + 4];
                a[mt][3] = As[row + 8 + g][kk + t + 4];
            }
#pragma unroll
            for (int nt = 0; nt < 4; nt++) {
                int col = wn * 32 + nt * 8 + g;
                b[nt][0] = Bs[col][kk + t];
                b[nt][1] = Bs[col][kk + t + 4];
            }
#pragma unroll
            for (int mt = 0; mt < 2; mt++)
#pragma unroll
                for (int nt = 0; nt < 4; nt++)
                    mma8(acc[mt][nt], a[mt], b[nt]);
        }
        __syncthreads();
    }

    // Epilogue: add bias, write out
#pragma unroll
    for (int mt = 0; mt < 2; mt++) {
#pragma unroll
        for (int nt = 0; nt < 4; nt++) {
            int mrow = m0 + wm * 32 + mt * 16 + g;   // rows mrow, mrow+8
            int ncol = n0 + wn * 32 + nt * 8 + 2 * t; // cols ncol, ncol+1
            float b0 = bias[ncol], b1 = bias[ncol + 1];
            float v00 = acc[mt][nt][0] + b0, v01 = acc[mt][nt][1] + b1;
            float v10 = acc[mt][nt][2] + b0, v11 = acc[mt][nt][3] + b1;
            if (!split) {
                float* p0 = Y + (size_t)mrow * E_DIM + ncol;
                float* p1 = Y + (size_t)(mrow + 8) * E_DIM + ncol;
                p0[0] = v00; p0[1] = v01;
                p1[0] = v10; p1[1] = v11;
            } else {
                // [B,H,T,D]: block of 128 rows stays within one batch (2048%128==0)
                int h = ncol >> 6, d = ncol & 63;
                int bb = mrow >> 11, tt = mrow & 2047;
                size_t o0 = ((size_t)(bb * NH + h) * T_SEQ + tt) * HD + d;
                size_t o1 = ((size_t)(bb * NH + h) * T_SEQ + tt + 8) * HD + d;
                Y[o0] = v00; Y[o0 + 1] = v01;
                Y[o1] = v10; Y[o1 + 1] = v11;
            }
        }
    }
}

// ---------------------------------------------------------------------------
// Flash attention: grid (T/64, B*H), 128 threads (4 warps).
// Each block: 64 queries x all 2048 keys, D=64, key tiles of 32.
// Warp w owns query rows [w*16, w*16+16). Online softmax, scale 1/8.
// Output written directly in [B,T,E] layout.
// ---------------------------------------------------------------------------
__global__ __launch_bounds__(128) void attn_kernel(
    const float* __restrict__ Q, const float* __restrict__ K,
    const float* __restrict__ V, float* __restrict__ O)
{
    __shared__ uint32_t sQ[64][68];       // tf32 bits, rows q, cols d
    __shared__ uint32_t sK[32][68];       // rows key, cols d
    __shared__ uint32_t sV[32][68];       // rows key, cols d
    __shared__ uint32_t sP[4][16][36];    // per-warp P tile (tf32 bits)

    const int tid  = threadIdx.x;
    const int warp = tid >> 5, lane = tid & 31;
    const int g    = lane >> 2, t = lane & 3;
    const int q0   = blockIdx.x * 64;
    const int bh   = blockIdx.y;

    const float* Qb = Q + ((size_t)bh * T_SEQ + q0) * HD;
    const float* Kb = K + (size_t)bh * T_SEQ * HD;
    const float* Vb = V + (size_t)bh * T_SEQ * HD;

    // Stage Q (64x64): 8 float4 per thread
#pragma unroll
    for (int i = 0; i < 8; i++) {
        int idx = tid + i * 128;
        int r = idx >> 4, c = (idx & 15) << 2;
        float4 v = *(const float4*)(Qb + (size_t)r * HD + c);
        sQ[r][c + 0] = f2tf(v.x); sQ[r][c + 1] = f2tf(v.y);
        sQ[r][c + 2] = f2tf(v.z); sQ[r][c + 3] = f2tf(v.w);
    }
    __syncthreads();

    // Q A-fragments live in registers for the whole kernel (8 k-steps x 4 regs)
    uint32_t qa[8][4];
#pragma unroll
    for (int kd = 0; kd < 8; kd++) {
        int row = warp * 16;
        qa[kd][0] = sQ[row + g][kd * 8 + t];
        qa[kd][1] = sQ[row + 8 + g][kd * 8 + t];
        qa[kd][2] = sQ[row + g][kd * 8 + t + 4];
        qa[kd][3] = sQ[row + 8 + g][kd * 8 + t + 4];
    }

    float m0v = -1e30f, m1v = -1e30f;   // running max: rows g, g+8
    float l0 = 0.f, l1 = 0.f;           // running denom
    float o[8][4];
#pragma unroll
    for (int df = 0; df < 8; df++)
#pragma unroll
        for (int r = 0; r < 4; r++) o[df][r] = 0.f;

    for (int j0 = 0; j0 < T_SEQ; j0 += 32) {
        __syncthreads();   // previous tile's sK/sV fully consumed
        // Load K,V tiles (32x64 each): 4 float4 per thread per tensor
#pragma unroll
        for (int i = 0; i < 4; i++) {
            int idx = tid + i * 128;
            int r = idx >> 4, c = (idx & 15) << 2;
            float4 vk = *(const float4*)(Kb + (size_t)(j0 + r) * HD + c);
            sK[r][c + 0] = f2tf(vk.x); sK[r][c + 1] = f2tf(vk.y);
            sK[r][c + 2] = f2tf(vk.z); sK[r][c + 3] = f2tf(vk.w);
            float4 vv = *(const float4*)(Vb + (size_t)(j0 + r) * HD + c);
            sV[r][c + 0] = f2tf(vv.x); sV[r][c + 1] = f2tf(vv.y);
            sV[r][c + 2] = f2tf(vv.z); sV[r][c + 3] = f2tf(vv.w);
        }
        __syncthreads();

        // S = Q K^T : 16 (rows) x 32 (keys), K-dim = 64 (8 steps)
        float s[4][4];
#pragma unroll
        for (int nt = 0; nt < 4; nt++)
#pragma unroll
            for (int r = 0; r < 4; r++) s[nt][r] = 0.f;

#pragma unroll
        for (int kd = 0; kd < 8; kd++) {
#pragma unroll
            for (int nt = 0; nt < 4; nt++) {
                uint32_t bfr[2];
                bfr[0] = sK[nt * 8 + g][kd * 8 + t];
                bfr[1] = sK[nt * 8 + g][kd * 8 + t + 4];
                mma8(s[nt], qa[kd], bfr);
            }
        }

        // Online softmax (scale = 1/sqrt(64) = 0.125)
        float mx0 = -1e30f, mx1 = -1e30f;
#pragma unroll
        for (int nt = 0; nt < 4; nt++) {
            s[nt][0] *= 0.125f; s[nt][1] *= 0.125f;
            s[nt][2] *= 0.125f; s[nt][3] *= 0.125f;
            mx0 = fmaxf(mx0, fmaxf(s[nt][0], s[nt][1]));
            mx1 = fmaxf(mx1, fmaxf(s[nt][2], s[nt][3]));
        }
        mx0 = fmaxf(mx0, __shfl_xor_sync(0xffffffffu, mx0, 1));
        mx0 = fmaxf(mx0, __shfl_xor_sync(0xffffffffu, mx0, 2));
        mx1 = fmaxf(mx1, __shfl_xor_sync(0xffffffffu, mx1, 1));
        mx1 = fmaxf(mx1, __shfl_xor_sync(0xffffffffu, mx1, 2));

        float mn0 = fmaxf(m0v, mx0), mn1 = fmaxf(m1v, mx1);
        float al0 = __expf(m0v - mn0), al1 = __expf(m1v - mn1);

        float rs0 = 0.f, rs1 = 0.f;
#pragma unroll
        for (int nt = 0; nt < 4; nt++) {
            s[nt][0] = __expf(s[nt][0] - mn0);
            s[nt][1] = __expf(s[nt][1] - mn0);
            s[nt][2] = __expf(s[nt][2] - mn1);
            s[nt][3] = __expf(s[nt][3] - mn1);
            rs0 += s[nt][0] + s[nt][1];
            rs1 += s[nt][2] + s[nt][3];
        }
        rs0 += __shfl_xor_sync(0xffffffffu, rs0, 1);
        rs0 += __shfl_xor_sync(0xffffffffu, rs0, 2);
        rs1 += __shfl_xor_sync(0xffffffffu, rs1, 1);
        rs1 += __shfl_xor_sync(0xffffffffu, rs1, 2);

        l0 = l0 * al0 + rs0;  l1 = l1 * al1 + rs1;
        m0v = mn0;            m1v = mn1;

#pragma unroll
        for (int df = 0; df < 8; df++) {
            o[df][0] *= al0; o[df][1] *= al0;
            o[df][2] *= al1; o[df][3] *= al1;
        }

        // Round-trip P through per-warp smem to get A-fragment layout
#pragma unroll
        for (int nt = 0; nt < 4; nt++) {
            sP[warp][g][nt * 8 + 2 * t]         = f2tf(s[nt][0]);
            sP[warp][g][nt * 8 + 2 * t + 1]     = f2tf(s[nt][1]);
            sP[warp][g + 8][nt * 8 + 2 * t]     = f2tf(s[nt][2]);
            sP[warp][g + 8][nt * 8 + 2 * t + 1] = f2tf(s[nt][3]);
        }
        __syncwarp();

        // O += P @ V : 16 x 64, K-dim = 32 keys (4 steps)
#pragma unroll
        for (int kk = 0; kk < 4; kk++) {
            uint32_t pa[4];
            pa[0] = sP[warp][g][kk * 8 + t];
            pa[1] = sP[warp][g + 8][kk * 8 + t];
            pa[2] = sP[warp][g][kk * 8 + t + 4];
            pa[3] = sP[warp][g + 8][kk * 8 + t + 4];
#pragma unroll
            for (int df = 0; df < 8; df++) {
                uint32_t bv[2];
                bv[0] = sV[kk * 8 + t][df * 8 + g];
                bv[1] = sV[kk * 8 + t + 4][df * 8 + g];
                mma8(o[df], pa, bv);
            }
        }
    }

    // Epilogue: normalize and write [B,T,E]
    float inv0 = 1.f / l0, inv1 = 1.f / l1;
    int bb = bh >> 4, h = bh & 15;
    int r0 = q0 + warp * 16 + g;
    int r1 = r0 + 8;
#pragma unroll
    for (int df = 0; df < 8; df++) {
        int d = df * 8 + 2 * t;
        size_t base0 = ((size_t)bb * T_SEQ + r0) * E_DIM + h * HD + d;
        size_t base1 = ((size_t)bb * T_SEQ + r1) * E_DIM + h * HD + d;
        O[base0]     = o[df][0] * inv0;
        O[base0 + 1] = o[df][1] * inv0;
        O[base1]     = o[df][2] * inv1;
        O[base1 + 1] = o[df][3] * inv1;
    }
}

// ---------------------------------------------------------------------------
// Launcher
// ---------------------------------------------------------------------------
extern "C" void kernel_launch(void* const* d_in, const int* in_sizes, int n_in,
                              void* d_out, int out_size)
{
    const float* x  = (const float*)d_in[0];
    const float* Wq = (const float*)d_in[1];
    const float* bq = (const float*)d_in[2];
    const float* Wk = (const float*)d_in[3];
    const float* bk = (const float*)d_in[4];
    const float* Wv = (const float*)d_in[5];
    const float* bv = (const float*)d_in[6];
    const float* Wo = (const float*)d_in[7];
    const float* bo = (const float*)d_in[8];

    float *q, *k, *v, *ctx;
    cudaGetSymbolAddress((void**)&q,   g_q);
    cudaGetSymbolAddress((void**)&k,   g_k);
    cudaGetSymbolAddress((void**)&v,   g_v);
    cudaGetSymbolAddress((void**)&ctx, g_ctx);

    dim3 ggrid(M_TOT / 128, E_DIM / 64);
    dim3 gblk(256);

    gemm_bias<<<ggrid, gblk>>>(x, Wq, bq, q, 1);
    gemm_bias<<<ggrid, gblk>>>(x, Wk, bk, k, 1);
    gemm_bias<<<ggrid, gblk>>>(x, Wv, bv, v, 1);

    attn_kernel<<<dim3(T_SEQ / 64, B_SZ * NH), 128>>>(q, k, v, ctx);

    gemm_bias<<<ggrid, gblk>>>(ctx, Wo, bo, (float*)d_out, 0);
}